// round 1
// baseline (speedup 1.0000x reference)
#include <cuda_runtime.h>

#define LATENT 16
#define HID 512
#define DD 64
#define NB 128
#define NG 128
#define OUTSZ 12610
#define OUTSZ_PAD 12612   // pad rows to multiple of 4 floats for alignment

// Scratch (device globals — no allocation allowed)
__device__ float g_h0[NB * HID];
__device__ float g_h1[NB * HID];
__device__ float g_wb[NB * OUTSZ_PAD];

__device__ __forceinline__ float leaky(float x) { return x > 0.0f ? x : 0.01f * x; }

// Accurate-enough fast sin: 2-step Cody-Waite range reduction + MUFU sin.
// |args| here stay < ~40 (k <= ~7), reduction error ~1e-9, MUFU err ~5e-7 on [-pi,pi].
__device__ __forceinline__ float fsin(float x) {
    float k = rintf(x * 0.15915494309189535f);
    x = fmaf(k, -6.28125f, x);                   // 2*pi hi (exact in fp32)
    x = fmaf(k, -1.9353071795864769e-3f, x);     // 2*pi lo
    return __sinf(x);
}

// ---------------------------------------------------------------------------
// Kernel 1: h0 = leaky_relu(z @ hw0 + hb0)    (128 x 512, K=16)
// ---------------------------------------------------------------------------
__global__ void k_h0(const float* __restrict__ z, const float* __restrict__ hw0,
                     const float* __restrict__ hb0) {
    int b = blockIdx.x;
    int j = threadIdx.x;  // 512 threads
    const float* zr = z + b * LATENT;
    float acc = hb0[j];
#pragma unroll
    for (int k = 0; k < LATENT; k++) acc = fmaf(zr[k], hw0[k * HID + j], acc);
    g_h0[b * HID + j] = leaky(acc);
}

// ---------------------------------------------------------------------------
// Generic tiled fp32 GEMM: C[M,N] = act(A[M,K] @ B[K,N] + bias[N])
// A,B,C row-major. C has leading dim ldc.
// ---------------------------------------------------------------------------
template <int BM, int BN, int BK, int TM, int TN, int ACT>
__global__ void __launch_bounds__((BM / TM) * (BN / TN))
gemm_bias(const float* __restrict__ A, const float* __restrict__ B,
          const float* __restrict__ bias, float* __restrict__ C,
          int M, int N, int K, int ldc) {
    __shared__ float As[BK][BM + 4];
    __shared__ float Bs[BK][BN];
    constexpr int TX = BN / TN;
    constexpr int TY = BM / TM;
    constexpr int NT = TX * TY;
    int tid = threadIdx.x;
    int tx = tid % TX, ty = tid / TX;
    int m0 = blockIdx.y * BM, n0 = blockIdx.x * BN;

    float acc[TM][TN];
#pragma unroll
    for (int i = 0; i < TM; i++)
#pragma unroll
        for (int j = 0; j < TN; j++) acc[i][j] = 0.0f;

    for (int k0 = 0; k0 < K; k0 += BK) {
        // A tile: BM x BK (rows of A are contiguous -> coalesced-ish)
#pragma unroll
        for (int idx = tid; idx < BM * BK; idx += NT) {
            int r = idx / BK, c = idx % BK;
            As[c][r] = A[(m0 + r) * K + k0 + c];
        }
        // B tile: BK x BN (coalesced), guard N tail
#pragma unroll
        for (int idx = tid; idx < BK * BN; idx += NT) {
            int r = idx / BN, c = idx % BN;
            int n = n0 + c;
            Bs[r][c] = (n < N) ? B[(k0 + r) * N + n] : 0.0f;
        }
        __syncthreads();
#pragma unroll
        for (int k = 0; k < BK; k++) {
            float ra[TM], rb[TN];
#pragma unroll
            for (int i = 0; i < TM; i++) ra[i] = As[k][ty * TM + i];
#pragma unroll
            for (int j = 0; j < TN; j++) rb[j] = Bs[k][tx * TN + j];
#pragma unroll
            for (int i = 0; i < TM; i++)
#pragma unroll
                for (int j = 0; j < TN; j++) acc[i][j] = fmaf(ra[i], rb[j], acc[i][j]);
        }
        __syncthreads();
    }

#pragma unroll
    for (int i = 0; i < TM; i++) {
        int m = m0 + ty * TM + i;
#pragma unroll
        for (int j = 0; j < TN; j++) {
            int n = n0 + tx * TN + j;
            if (n < N) {
                float v = acc[i][j] + bias[n];
                if (ACT) v = leaky(v);
                C[m * ldc + n] = v;
            }
        }
    }
}

// ---------------------------------------------------------------------------
// Kernel 3: per-(b,g) decoder MLP. One block per b, one thread per g.
// wb row is repacked into an aligned smem layout:
//   [0 .. 12288)   : W1,W2,W3  (3 x 64x64, row-major, 16B-aligned)
//   [12288..12352) : W0 (64)
//   [12352..12544) : b1,b2,b3 (3 x 64)
//   [12544..12608) : W4 (64)
//   [12608]        : b0 (scalar)
//   [12609]        : b4 (scalar)
// ---------------------------------------------------------------------------
#define OFF_W0 12288
#define OFF_B  12352
#define OFF_W4 12544

__global__ void __launch_bounds__(128)
k_decode(const float* __restrict__ logP, float* __restrict__ out) {
    extern __shared__ float wb[];
    int b = blockIdx.x;
    int tid = threadIdx.x;
    const float* src = g_wb + (size_t)b * OUTSZ_PAD;

    // Repack wb row into aligned smem layout (coalesced scalar loads)
    for (int l = 0; l < 3; l++)
        for (int i = tid; i < DD * DD; i += 128)
            wb[l * DD * DD + i] = src[65 + l * 4160 + i];
    if (tid < DD) {
        wb[OFF_W0 + tid] = src[tid];                      // W0
        wb[OFF_B + 0 * DD + tid] = src[4161 + tid];       // b1
        wb[OFF_B + 1 * DD + tid] = src[8321 + tid];       // b2
        wb[OFF_B + 2 * DD + tid] = src[12481 + tid];      // b3
        wb[OFF_W4 + tid] = src[12545 + tid];              // W4
    }
    if (tid == 0) { wb[12608] = src[64]; wb[12609] = src[12609]; }
    __syncthreads();

    int g = tid;
    float xin = logP[b * NG + g];

    float x[DD];
    float b0 = wb[12608];
#pragma unroll
    for (int j = 0; j < DD; j++)
        x[j] = fsin(30.0f * fmaf(xin, wb[OFF_W0 + j], b0));

#pragma unroll 1
    for (int layer = 0; layer < 3; layer++) {
        const float* W = wb + layer * DD * DD;
        const float* bs = wb + OFF_B + layer * DD;
        float y[DD];
#pragma unroll
        for (int j = 0; j < DD; j += 4) {
            float a0 = bs[j], a1 = bs[j + 1], a2 = bs[j + 2], a3 = bs[j + 3];
#pragma unroll
            for (int i = 0; i < DD; i++) {
                float4 w = *(const float4*)(W + i * DD + j);  // smem broadcast
                float xi = x[i];
                a0 = fmaf(xi, w.x, a0);
                a1 = fmaf(xi, w.y, a1);
                a2 = fmaf(xi, w.z, a2);
                a3 = fmaf(xi, w.w, a3);
            }
            y[j] = fsin(a0); y[j + 1] = fsin(a1); y[j + 2] = fsin(a2); y[j + 3] = fsin(a3);
        }
#pragma unroll
        for (int j = 0; j < DD; j++) x[j] = y[j];
    }

    float acc = wb[12609];
#pragma unroll
    for (int i = 0; i < DD; i++) acc = fmaf(x[i], wb[OFF_W4 + i], acc);

    out[b * NG + g] = fmaf(acc, 500.0f, 1500.0f);
}

// ---------------------------------------------------------------------------
extern "C" void kernel_launch(void* const* d_in, const int* in_sizes, int n_in,
                              void* d_out, int out_size) {
    (void)in_sizes; (void)n_in; (void)out_size;
    const float* z    = (const float*)d_in[0];
    const float* logP = (const float*)d_in[1];
    const float* hw0  = (const float*)d_in[2];
    const float* hb0  = (const float*)d_in[3];
    const float* hw1  = (const float*)d_in[4];
    const float* hb1  = (const float*)d_in[5];
    const float* hw2  = (const float*)d_in[6];
    const float* hb2  = (const float*)d_in[7];
    float* out = (float*)d_out;

    float *p_h0, *p_h1, *p_wb;
    cudaGetSymbolAddress((void**)&p_h0, g_h0);
    cudaGetSymbolAddress((void**)&p_h1, g_h1);
    cudaGetSymbolAddress((void**)&p_wb, g_wb);

    static_assert(OUTSZ_PAD * 4 == 50448, "smem size");
    cudaFuncSetAttribute(k_decode, cudaFuncAttributeMaxDynamicSharedMemorySize, 50448);

    // 1) h0 = leaky(z @ hw0 + hb0)
    k_h0<<<NB, HID>>>(z, hw0, hb0);

    // 2) h1 = leaky(h0 @ hw1 + hb1)   M=128,N=512,K=512
    {
        dim3 grid(HID / 32, NB / 32);
        gemm_bias<32, 32, 32, 2, 2, 1><<<grid, 256>>>(p_h0, hw1, hb1, p_h1,
                                                      NB, HID, HID, HID);
    }

    // 3) wb = h1 @ hw2 + hb2          M=128,N=12610,K=512
    {
        dim3 grid((OUTSZ + 63) / 64, NB / 64);
        gemm_bias<64, 64, 16, 4, 4, 0><<<grid, 256>>>(p_h1, hw2, hb2, p_wb,
                                                      NB, OUTSZ, HID, OUTSZ_PAD);
    }

    // 4) decoder: one block per b, one thread per g
    k_decode<<<NB, 128, 50448>>>(logP, out);
}

// round 2
// speedup vs baseline: 1.0051x; 1.0051x over previous
#include <cuda_runtime.h>

#define LATENT 16
#define HID 512
#define DD 64
#define NB 128
#define NG 128
#define OUTSZ 12610
#define OUTSZ_PAD 12612   // pad rows to multiple of 4 floats for alignment

// Scratch (device globals — no allocation allowed)
__device__ float g_h0[NB * HID];
__device__ float g_h1[NB * HID];
__device__ float g_wb[NB * OUTSZ_PAD];

__device__ __forceinline__ float leaky(float x) { return x > 0.0f ? x : 0.01f * x; }

// Accurate-enough fast sin: 2-step Cody-Waite range reduction + MUFU sin.
// |args| here stay < ~40 (k <= ~7), reduction error ~1e-9, MUFU err ~5e-7 on [-pi,pi].
__device__ __forceinline__ float fsin(float x) {
    float k = rintf(x * 0.15915494309189535f);
    x = fmaf(k, -6.28125f, x);                   // 2*pi hi (exact in fp32)
    x = fmaf(k, -1.9353071795864769e-3f, x);     // 2*pi lo
    return __sinf(x);
}

// ---------------------------------------------------------------------------
// Kernel 1: h0 = leaky_relu(z @ hw0 + hb0)    (128 x 512, K=16)
// ---------------------------------------------------------------------------
__global__ void k_h0(const float* __restrict__ z, const float* __restrict__ hw0,
                     const float* __restrict__ hb0) {
    int b = blockIdx.x;
    int j = threadIdx.x;  // 512 threads
    const float* zr = z + b * LATENT;
    float acc = hb0[j];
#pragma unroll
    for (int k = 0; k < LATENT; k++) acc = fmaf(zr[k], hw0[k * HID + j], acc);
    g_h0[b * HID + j] = leaky(acc);
}

// ---------------------------------------------------------------------------
// Generic tiled fp32 GEMM: C[M,N] = act(A[M,K] @ B[K,N] + bias[N])
// A,B,C row-major. C has leading dim ldc.
// ---------------------------------------------------------------------------
template <int BM, int BN, int BK, int TM, int TN, int ACT>
__global__ void __launch_bounds__((BM / TM) * (BN / TN))
gemm_bias(const float* __restrict__ A, const float* __restrict__ B,
          const float* __restrict__ bias, float* __restrict__ C,
          int M, int N, int K, int ldc) {
    __shared__ float As[BK][BM + 4];
    __shared__ float Bs[BK][BN];
    constexpr int TX = BN / TN;
    constexpr int TY = BM / TM;
    constexpr int NT = TX * TY;
    int tid = threadIdx.x;
    int tx = tid % TX, ty = tid / TX;
    int m0 = blockIdx.y * BM, n0 = blockIdx.x * BN;

    float acc[TM][TN];
#pragma unroll
    for (int i = 0; i < TM; i++)
#pragma unroll
        for (int j = 0; j < TN; j++) acc[i][j] = 0.0f;

    for (int k0 = 0; k0 < K; k0 += BK) {
        // A tile: BM x BK (rows of A are contiguous -> coalesced-ish)
#pragma unroll
        for (int idx = tid; idx < BM * BK; idx += NT) {
            int r = idx / BK, c = idx % BK;
            As[c][r] = A[(m0 + r) * K + k0 + c];
        }
        // B tile: BK x BN (coalesced), guard N tail
#pragma unroll
        for (int idx = tid; idx < BK * BN; idx += NT) {
            int r = idx / BN, c = idx % BN;
            int n = n0 + c;
            Bs[r][c] = (n < N) ? B[(k0 + r) * N + n] : 0.0f;
        }
        __syncthreads();
#pragma unroll
        for (int k = 0; k < BK; k++) {
            float ra[TM], rb[TN];
#pragma unroll
            for (int i = 0; i < TM; i++) ra[i] = As[k][ty * TM + i];
#pragma unroll
            for (int j = 0; j < TN; j++) rb[j] = Bs[k][tx * TN + j];
#pragma unroll
            for (int i = 0; i < TM; i++)
#pragma unroll
                for (int j = 0; j < TN; j++) acc[i][j] = fmaf(ra[i], rb[j], acc[i][j]);
        }
        __syncthreads();
    }

#pragma unroll
    for (int i = 0; i < TM; i++) {
        int m = m0 + ty * TM + i;
#pragma unroll
        for (int j = 0; j < TN; j++) {
            int n = n0 + tx * TN + j;
            if (n < N) {
                float v = acc[i][j] + bias[n];
                if (ACT) v = leaky(v);
                C[m * ldc + n] = v;
            }
        }
    }
}

// ---------------------------------------------------------------------------
// Kernel 3: per-(b,g) decoder MLP. One block per b, one thread per g.
// wb row is repacked into an aligned smem layout:
//   [0 .. 12288)   : W1,W2,W3  (3 x 64x64, row-major, 16B-aligned)
//   [12288..12352) : W0 (64)
//   [12352..12544) : b1,b2,b3 (3 x 64)
//   [12544..12608) : W4 (64)
//   [12608]        : b0 (scalar)
//   [12609]        : b4 (scalar)
// ---------------------------------------------------------------------------
#define OFF_W0 12288
#define OFF_B  12352
#define OFF_W4 12544

__global__ void __launch_bounds__(128)
k_decode(const float* __restrict__ logP, float* __restrict__ out) {
    extern __shared__ float wb[];
    int b = blockIdx.x;
    int tid = threadIdx.x;
    const float* src = g_wb + (size_t)b * OUTSZ_PAD;

    // Repack wb row into aligned smem layout (coalesced scalar loads)
    for (int l = 0; l < 3; l++)
        for (int i = tid; i < DD * DD; i += 128)
            wb[l * DD * DD + i] = src[65 + l * 4160 + i];
    if (tid < DD) {
        wb[OFF_W0 + tid] = src[tid];                      // W0
        wb[OFF_B + 0 * DD + tid] = src[4161 + tid];       // b1
        wb[OFF_B + 1 * DD + tid] = src[8321 + tid];       // b2
        wb[OFF_B + 2 * DD + tid] = src[12481 + tid];      // b3
        wb[OFF_W4 + tid] = src[12545 + tid];              // W4
    }
    if (tid == 0) { wb[12608] = src[64]; wb[12609] = src[12609]; }
    __syncthreads();

    int g = tid;
    float xin = logP[b * NG + g];

    float x[DD];
    float b0 = wb[12608];
#pragma unroll
    for (int j = 0; j < DD; j++)
        x[j] = fsin(30.0f * fmaf(xin, wb[OFF_W0 + j], b0));

#pragma unroll 1
    for (int layer = 0; layer < 3; layer++) {
        const float* W = wb + layer * DD * DD;
        const float* bs = wb + OFF_B + layer * DD;
        float y[DD];
#pragma unroll
        for (int j = 0; j < DD; j += 4) {
            float a0 = bs[j], a1 = bs[j + 1], a2 = bs[j + 2], a3 = bs[j + 3];
#pragma unroll
            for (int i = 0; i < DD; i++) {
                float4 w = *(const float4*)(W + i * DD + j);  // smem broadcast
                float xi = x[i];
                a0 = fmaf(xi, w.x, a0);
                a1 = fmaf(xi, w.y, a1);
                a2 = fmaf(xi, w.z, a2);
                a3 = fmaf(xi, w.w, a3);
            }
            y[j] = fsin(a0); y[j + 1] = fsin(a1); y[j + 2] = fsin(a2); y[j + 3] = fsin(a3);
        }
#pragma unroll
        for (int j = 0; j < DD; j++) x[j] = y[j];
    }

    float acc = wb[12609];
#pragma unroll
    for (int i = 0; i < DD; i++) acc = fmaf(x[i], wb[OFF_W4 + i], acc);

    out[b * NG + g] = fmaf(acc, 500.0f, 1500.0f);
}

// ---------------------------------------------------------------------------
extern "C" void kernel_launch(void* const* d_in, const int* in_sizes, int n_in,
                              void* d_out, int out_size) {
    (void)in_sizes; (void)n_in; (void)out_size;
    const float* z    = (const float*)d_in[0];
    const float* logP = (const float*)d_in[1];
    const float* hw0  = (const float*)d_in[2];
    const float* hb0  = (const float*)d_in[3];
    const float* hw1  = (const float*)d_in[4];
    const float* hb1  = (const float*)d_in[5];
    const float* hw2  = (const float*)d_in[6];
    const float* hb2  = (const float*)d_in[7];
    float* out = (float*)d_out;

    float *p_h0, *p_h1, *p_wb;
    cudaGetSymbolAddress((void**)&p_h0, g_h0);
    cudaGetSymbolAddress((void**)&p_h1, g_h1);
    cudaGetSymbolAddress((void**)&p_wb, g_wb);

    static_assert(OUTSZ_PAD * 4 == 50448, "smem size");
    cudaFuncSetAttribute(k_decode, cudaFuncAttributeMaxDynamicSharedMemorySize, 50448);

    // 1) h0 = leaky(z @ hw0 + hb0)
    k_h0<<<NB, HID>>>(z, hw0, hb0);

    // 2) h1 = leaky(h0 @ hw1 + hb1)   M=128,N=512,K=512
    {
        dim3 grid(HID / 32, NB / 32);
        gemm_bias<32, 32, 32, 2, 2, 1><<<grid, 256>>>(p_h0, hw1, hb1, p_h1,
                                                      NB, HID, HID, HID);
    }

    // 3) wb = h1 @ hw2 + hb2          M=128,N=12610,K=512
    {
        dim3 grid((OUTSZ + 63) / 64, NB / 64);
        gemm_bias<64, 64, 16, 4, 4, 0><<<grid, 256>>>(p_h1, hw2, hb2, p_wb,
                                                      NB, OUTSZ, HID, OUTSZ_PAD);
    }

    // 4) decoder: one block per b, one thread per g
    k_decode<<<NB, 128, 50448>>>(logP, out);
}